// round 16
// baseline (speedup 1.0000x reference)
#include <cuda_runtime.h>

static constexpr int BATCH = 8;
static constexpr int SEQ   = 16384;
static constexpr int CH    = 256;
static constexpr int TOPN  = 2048;
static constexpr int ROWS  = BATCH * SEQ;     // 131072
static constexpr int QUADS = ROWS / 4;        // 32768

static constexpr int K1_GRID    = 444;        // 148 SMs * 3 resident CTAs
static constexpr int K1_THREADS = 256;        // 8 warps
static constexpr int K1_WARPS_TOTAL = K1_GRID * (K1_THREADS / 32);  // 3552

static constexpr int SEL_THREADS = 512;       // 16 warps, 32 elems/thread

__device__ float g_score[ROWS];
__device__ float g_psum[K1_GRID];
__device__ float g_psq[K1_GRID];
__device__ unsigned g_idx[BATCH * TOPN];
__device__ unsigned long long g_keys[ROWS];   // slow-path scratch (global)

// ---------------------------------------------------------------------------
// K1: persistent grid-stride. A warp covers 4 rows, 8 lanes per row
// (lane = 8*subrow + pos). 8 front-batched float4 streaming loads per thread;
// row reduce = 3-step shfl butterfly (4 rows simultaneously in one register).
// Scores stored with DEFAULT caching (L2-resident for select's re-read).
// ---------------------------------------------------------------------------
__global__ __launch_bounds__(K1_THREADS, 3) void score_kernel(const float* __restrict__ x,
                                                              const float* __restrict__ w,
                                                              const float* __restrict__ bias) {
    const int warp   = threadIdx.x >> 5;
    const int lane   = threadIdx.x & 31;
    const int subrow = lane >> 3;
    const int pos    = lane & 7;
    const int gw     = blockIdx.x * (K1_THREADS / 32) + warp;

    const float4* wv = (const float4*)w;
    float4 W[8];
#pragma unroll
    for (int j = 0; j < 8; j++) W[j] = wv[pos + 8*j];
    const float bb = bias[0];

    float S = 0.f, Q = 0.f;

    for (int quad = gw; quad < QUADS; quad += K1_WARPS_TOTAL) {
        const size_t row = (size_t)quad * 4 + subrow;
        const float4* xb = (const float4*)(x + row * CH);

        float4 v[8];
#pragma unroll
        for (int j = 0; j < 8; j++) v[j] = __ldcs(xb + pos + 8*j);

        float d = 0.f;
#pragma unroll
        for (int j = 0; j < 8; j++)
            d += v[j].x*W[j].x + v[j].y*W[j].y + v[j].z*W[j].z + v[j].w*W[j].w;

        d += __shfl_xor_sync(0xffffffffu, d, 4);
        d += __shfl_xor_sync(0xffffffffu, d, 2);
        d += __shfl_xor_sync(0xffffffffu, d, 1);

        if (pos == 0) {
            float c = d + bb;
            g_score[row] = c;          // default caching: stays L2-hot
            S += c;
            Q += c * c;
        }
    }

#pragma unroll
    for (int off = 16; off > 0; off >>= 1) {
        S += __shfl_xor_sync(0xffffffffu, S, off);
        Q += __shfl_xor_sync(0xffffffffu, Q, off);
    }
    __shared__ float ws[K1_THREADS / 32], wq[K1_THREADS / 32];
    if (lane == 0) { ws[warp] = S; wq[warp] = Q; }
    __syncthreads();
    if (threadIdx.x < 32) {
        float s = (threadIdx.x < K1_THREADS / 32) ? ws[threadIdx.x] : 0.f;
        float q = (threadIdx.x < K1_THREADS / 32) ? wq[threadIdx.x] : 0.f;
#pragma unroll
        for (int off = 4; off > 0; off >>= 1) {
            s += __shfl_xor_sync(0xffffffffu, s, off);
            q += __shfl_xor_sync(0xffffffffu, q, off);
        }
        if (threadIdx.x == 0) { g_psum[blockIdx.x] = s; g_psq[blockIdx.x] = q; }
    }
}

// ---------------------------------------------------------------------------
// K2: one CTA (512 threads) per batch. Fast path: ReLU zeros (normalized
// <= 0) lead a stable ascending argsort in index order -> stream compaction
// of the first TOPN qualifying indices (32 elems/thread). Slow path
// (practically unreachable): iterative global argmin on stable keys.
// ---------------------------------------------------------------------------
__global__ __launch_bounds__(SEL_THREADS) void select_kernel(const float* __restrict__ gamma,
                                                             const float* __restrict__ beta) {
    __shared__ float red1[SEL_THREADS], red2[SEL_THREADS];
    __shared__ unsigned warpsum[16], warpexcl[16];
    __shared__ unsigned total_s;

    const int tid  = threadIdx.x;
    const int lane = tid & 31;
    const int warp = tid >> 5;
    const int b    = blockIdx.x;

    // --- mean / var from K1 partials ---
    {
        float S = (tid < K1_GRID) ? g_psum[tid] : 0.f;
        float Q = (tid < K1_GRID) ? g_psq[tid]  : 0.f;
        red1[tid] = S; red2[tid] = Q;
    }
    __syncthreads();
    for (int off = 256; off > 0; off >>= 1) {
        if (tid < off) { red1[tid] += red1[tid + off]; red2[tid] += red2[tid + off]; }
        __syncthreads();
    }
    float mean = red1[0] / (float)ROWS;
    float var  = red2[0] / (float)ROWS - mean * mean;
    if (var < 0.f) var = 0.f;
    float scale = rsqrtf(var + 1e-5f) * gamma[0];
    float shift = beta[0] - mean * scale;

    // --- compaction scan: 32 elements per thread ---
    const float* sc = g_score + (size_t)b * SEQ;
    const int base = tid * 32;
    const float4* p4 = (const float4*)(sc + base);
    unsigned m0 = 0;
#pragma unroll
    for (int j = 0; j < 8; j++) {
        float4 v = p4[j];
        if (fmaf(v.x, scale, shift) <= 0.f) m0 |= 1u << (4*j + 0);
        if (fmaf(v.y, scale, shift) <= 0.f) m0 |= 1u << (4*j + 1);
        if (fmaf(v.z, scale, shift) <= 0.f) m0 |= 1u << (4*j + 2);
        if (fmaf(v.w, scale, shift) <= 0.f) m0 |= 1u << (4*j + 3);
    }
    const unsigned c = (unsigned)__popc(m0);

    unsigned incl = c;
#pragma unroll
    for (int off = 1; off < 32; off <<= 1) {
        unsigned n = __shfl_up_sync(0xffffffffu, incl, off);
        if (lane >= off) incl += n;
    }
    if (lane == 31) warpsum[warp] = incl;
    __syncthreads();
    if (tid < 16) {
        unsigned wv = warpsum[tid];
        unsigned wincl = wv;
#pragma unroll
        for (int off = 1; off < 16; off <<= 1) {
            unsigned n = __shfl_up_sync(0x0000ffffu, wincl, off);
            if (tid >= off) wincl += n;
        }
        warpexcl[tid] = wincl - wv;
        if (tid == 15) total_s = wincl;
    }
    __syncthreads();
    const unsigned T = total_s;

    if (T >= (unsigned)TOPN) {
        unsigned r = warpexcl[warp] + (incl - c);
        if (r < (unsigned)TOPN) {
#pragma unroll
            for (int j = 0; j < 32; j++) {
                if (m0 & (1u << j)) {
                    if (r < (unsigned)TOPN) g_idx[b * TOPN + r] = (unsigned)(base + j);
                    r++;
                }
            }
        }
        return;
    }

    // ===== slow path: iterative global argmin (correctness-only) =====
    unsigned long long* kb = g_keys + (size_t)b * SEQ;
    for (int i = tid; i < SEQ; i += SEL_THREADS) {
        float r = fmaxf(0.f, fmaf(sc[i], scale, shift));
        kb[i] = ((unsigned long long)__float_as_uint(r) << 14) | (unsigned)i;
    }
    __syncthreads();
    __shared__ unsigned long long mv[SEL_THREADS];
    __shared__ int mp[SEL_THREADS];
    for (int r = 0; r < TOPN; r++) {
        unsigned long long best = ~0ULL; int bp = 0;
        for (int i = tid; i < SEQ; i += SEL_THREADS) {
            unsigned long long k = kb[i];
            if (k < best) { best = k; bp = i; }
        }
        mv[tid] = best; mp[tid] = bp;
        __syncthreads();
        for (int off = 256; off > 0; off >>= 1) {
            if (tid < off && mv[tid + off] < mv[tid]) {
                mv[tid] = mv[tid + off]; mp[tid] = mp[tid + off];
            }
            __syncthreads();
        }
        if (tid == 0) {
            g_idx[b * TOPN + r] = (unsigned)(mv[0] & 0x3fffu);
            kb[mp[0]] = ~0ULL;
        }
        __syncthreads();
    }
}

// ---------------------------------------------------------------------------
// K3: gather rows: out[b, r, :] = x_select[b, idx[b,r], :]
// 512 CTAs x 128 threads: 16 rows/CTA, 8 threads/row, 8 front-batched float4
// per thread; no smem staging / barrier in the dependent chain.
// ---------------------------------------------------------------------------
__global__ __launch_bounds__(128) void gather_kernel(const float* __restrict__ xs,
                                                     float* __restrict__ out) {
    const int t    = threadIdx.x;
    const int lrow = t >> 3;                     // 0..15
    const int pos  = t & 7;                      // 0..7
    const int rid  = blockIdx.x * 16 + lrow;     // 0 .. BATCH*TOPN-1
    const int b    = rid >> 11;                  // TOPN == 2048

    const unsigned idx = __ldg(&g_idx[rid]);
    const float4* src = (const float4*)(xs + ((size_t)b * SEQ + idx) * CH);
    float4* dst = (float4*)(out + (size_t)rid * CH);

    float4 v[8];
#pragma unroll
    for (int j = 0; j < 8; j++) v[j] = __ldcs(src + pos + 8*j);
#pragma unroll
    for (int j = 0; j < 8; j++) __stcs(dst + pos + 8*j, v[j]);
}

// ---------------------------------------------------------------------------
extern "C" void kernel_launch(void* const* d_in, const int* in_sizes, int n_in,
                              void* d_out, int out_size) {
    const float* x_in  = (const float*)d_in[0];
    const float* x_sel = (const float*)d_in[1];
    const float* w     = (const float*)d_in[2];
    const float* bias  = (const float*)d_in[3];
    const float* gamma = (const float*)d_in[4];
    const float* beta  = (const float*)d_in[5];
    float* out = (float*)d_out;

    score_kernel<<<K1_GRID, K1_THREADS>>>(x_in, w, bias);
    select_kernel<<<BATCH, SEL_THREADS>>>(gamma, beta);
    gather_kernel<<<(BATCH * TOPN) / 16, 128>>>(x_sel, out);
}